// round 3
// baseline (speedup 1.0000x reference)
#include <cuda_runtime.h>
#include <math.h>

// ---------------- problem constants ----------------
#define NVID  4
#define FPV   64
#define TOTF  256
#define NRECS 240
#define TTXT  32
#define EPAD  304      // 300 padded to 304 for float4
#define HIDN  256
#define NCLS  20
#define OCC   32
#define MROWS 7680     // 240*32

// ---------------- device-global scratch (allocation-free rule) ----------------
__device__ float g_part[NVID*OCC*FPV*196];   // conv + HW-pool result [v][oc][d][14][14]
__device__ float g_fdot[TOTF*NCLS];          // per-frame pooled-feature . lin_w
__device__ float g_x0[MROWS*EPAD];           // embedded text, K padded
__device__ float g_wpad[2*1024*EPAD];        // Wih_l0 padded 300->304
__device__ float g_pre[2*MROWS*1024];        // input-proj gates per dir (reused per layer)
__device__ float g_out0[MROWS*512];          // layer0 output [row][t][512]
__device__ float g_out1[MROWS*512];          // layer1 output
__device__ float g_h[2][2][NRECS*HIDN];      // [parity][dir][row*256+j]
__device__ float g_c[2][NRECS*HIDN];         // [dir]
__device__ float g_avg[NRECS*512];

// ================= Conv3D + HW max-pool (fused) =================
// grid (14 ph, 32 dpair, v*2+half), 448 threads.
#define PATCH_ROW 122
#define PATCH_SZ  (3*4*21*PATCH_ROW)
#define WSZ       (32*441)
#define CONV_SMEM ((PATCH_SZ + WSZ) * 4)

__global__ __launch_bounds__(448,1) void conv_pool_kernel(
    const float* __restrict__ img, const float* __restrict__ cw)
{
    extern __shared__ float sh[];
    float* patch = sh;
    float* ws    = sh + PATCH_SZ;
    const int ph = blockIdx.x;
    const int d0 = blockIdx.y * 2;
    const int v  = blockIdx.z >> 1, half = blockIdx.z & 1;
    const int tid = threadIdx.x;

    for (int i = tid; i < WSZ; i += 448) ws[i] = cw[i];

    const int NLOAD = 3*4*21*117;
    for (int i = tid; i < NLOAD; i += 448) {
        int c  = i % 117; int rr = i / 117;
        int r  = rr % 21; int dds = (rr / 21) & 3; int ci = rr / 84;
        int iw = 112*half - 3 + c;
        int ih = 16*ph    - 3 + r;
        int dd = d0 - 1 + dds;
        float val = 0.f;
        if ((unsigned)dd < 64u && (unsigned)ih < 224u && (unsigned)iw < 224u)
            val = img[(((v*64 + dd)*3 + ci)*224 + ih)*224 + iw];
        patch[((ci*4 + dds)*21 + r)*PATCH_ROW + (c & 1)*61 + (c >> 1)] = val;
    }
    __syncthreads();

    const int dloc = tid / 224; const int rem = tid % 224;
    const int pwl  = rem >> 5;  const int lane = rem & 31;
    const int ocg  = lane >> 3; const int hh  = lane & 7;

    float acc[8][8];
    #pragma unroll
    for (int r = 0; r < 8; r++)
        #pragma unroll
        for (int j = 0; j < 8; j++) acc[r][j] = 0.f;

    for (int ci = 0; ci < 3; ci++)
    for (int kd = 0; kd < 3; kd++)
    #pragma unroll 1
    for (int kh = 0; kh < 7; kh++) {
        const float* prow = &patch[((ci*4 + dloc + kd)*21 + 2*hh + kh)*PATCH_ROW];
        const float* wrow = &ws[(ocg*8)*441 + ci*147 + kd*49 + kh*7];
        #pragma unroll
        for (int kw = 0; kw < 7; kw++) {
            const float* xp = prow + (kw & 1)*61 + 8*pwl + (kw >> 1);
            float xv[8];
            #pragma unroll
            for (int j = 0; j < 8; j++) xv[j] = xp[j];
            #pragma unroll
            for (int r = 0; r < 8; r++) {
                float wv = wrow[r*441 + kw];
                #pragma unroll
                for (int j = 0; j < 8; j++) acc[r][j] = fmaf(wv, xv[j], acc[r][j]);
            }
        }
    }

    const int d  = d0 + dloc;
    const int pw = half*7 + pwl;
    #pragma unroll
    for (int r = 0; r < 8; r++) {
        float mx = acc[r][0];
        #pragma unroll
        for (int j = 1; j < 8; j++) mx = fmaxf(mx, acc[r][j]);
        mx = fmaxf(mx, __shfl_xor_sync(0xffffffffu, mx, 4));
        mx = fmaxf(mx, __shfl_xor_sync(0xffffffffu, mx, 2));
        mx = fmaxf(mx, __shfl_xor_sync(0xffffffffu, mx, 1));
        if (hh == 0) {
            int oc = ocg*8 + r;
            g_part[(((v*OCC + oc)*FPV + d)*14 + ph)*14 + pw] = mx;
        }
    }
}

// ================= D-pool + (pooled features) . lin_w -> g_fdot =================
__global__ void fdot_kernel(const float* __restrict__ cb, const float* __restrict__ lw)
{
    const int f = blockIdx.x;            // 256
    const int v = f >> 6, d = f & 63;
    const int tid = threadIdx.x;         // 256
    float acc[NCLS];
    #pragma unroll
    for (int c = 0; c < NCLS; c++) acc[c] = 0.f;

    for (int k = tid; k < 6272; k += 256) {
        int oc = k / 196; int rem2 = k % 196;
        const float* base = g_part + (v*OCC + oc)*FPV*196 + rem2;
        float val = base[d*196];
        if (d > 0)  val = fmaxf(val, base[(d-1)*196]);
        if (d < 63) val = fmaxf(val, base[(d+1)*196]);
        val += cb[oc];
        #pragma unroll
        for (int c = 0; c < NCLS; c++) acc[c] = fmaf(val, lw[c*6784 + k], acc[c]);
    }
    #pragma unroll
    for (int c = 0; c < NCLS; c++)
        for (int off = 16; off; off >>= 1)
            acc[c] += __shfl_xor_sync(0xffffffffu, acc[c], off);

    __shared__ float red[8][NCLS];
    const int wid = tid >> 5, lane = tid & 31;
    if (lane == 0)
        #pragma unroll
        for (int c = 0; c < NCLS; c++) red[wid][c] = acc[c];
    __syncthreads();
    if (tid < NCLS) {
        float s = 0.f;
        #pragma unroll
        for (int w = 0; w < 8; w++) s += red[w][tid];
        g_fdot[f*NCLS + tid] = s;
    }
}

// ================= Embedding gather (pad K to 304) =================
__global__ void embed_kernel(const int* __restrict__ txt, const float* __restrict__ emb)
{
    const int m = blockIdx.x;            // 7680 = row*32 + t
    const int tok = txt[m];
    const float* e = emb + (long long)tok * 300;
    for (int k = threadIdx.x; k < EPAD; k += 128)
        g_x0[m*EPAD + k] = (k < 300) ? e[k] : 0.f;
}

__global__ void pad_wih_kernel(const float* __restrict__ Wih0)
{
    const int row = blockIdx.x;          // 2048 = dir*1024 + gate
    const float* src = Wih0 + row * 300;
    for (int k = threadIdx.x; k < EPAD; k += 128)
        g_wpad[row*EPAD + k] = (k < 300) ? src[k] : 0.f;
}

// ================= SGEMM: pre = X @ Wih^T + bih + bhh =================
// grid (60, 8, 2 dirs), 256 threads, 128x128 tile, 8x8 per thread.
__global__ __launch_bounds__(256,2) void gemm_kernel(
    int layer, const float* __restrict__ Bext,
    const float* __restrict__ bih, const float* __restrict__ bhh)
{
    const int K = layer ? 512 : EPAD;
    const float* A = layer ? g_out0 : g_x0;
    const float* B = (layer ? Bext : (const float*)g_wpad) + blockIdx.z * 1024 * K;
    float* C = g_pre + blockIdx.z * (MROWS * 1024);
    const int m0 = blockIdx.x * 128, n0 = blockIdx.y * 128;

    __shared__ float As[8*132];
    __shared__ float Bs[8*132];
    const int tid = threadIdx.x;
    const int lr = tid >> 1;
    const int lk = (tid & 1) * 4;
    const int ty = tid >> 4, tx = tid & 15;
    const float* Arow = A + (m0 + lr)*K + lk;
    const float* Brow = B + (n0 + lr)*K + lk;

    float acc[8][8];
    #pragma unroll
    for (int i = 0; i < 8; i++)
        #pragma unroll
        for (int j = 0; j < 8; j++) acc[i][j] = 0.f;

    for (int k0 = 0; k0 < K; k0 += 8) {
        float4 va = *(const float4*)(Arow + k0);
        float4 vb = *(const float4*)(Brow + k0);
        __syncthreads();
        As[(lk+0)*132 + lr] = va.x; As[(lk+1)*132 + lr] = va.y;
        As[(lk+2)*132 + lr] = va.z; As[(lk+3)*132 + lr] = va.w;
        Bs[(lk+0)*132 + lr] = vb.x; Bs[(lk+1)*132 + lr] = vb.y;
        Bs[(lk+2)*132 + lr] = vb.z; Bs[(lk+3)*132 + lr] = vb.w;
        __syncthreads();
        #pragma unroll
        for (int kk = 0; kk < 8; kk++) {
            float a[8], b[8];
            float4 t0 = *(const float4*)&As[kk*132 + ty*8];
            float4 t1 = *(const float4*)&As[kk*132 + ty*8 + 4];
            float4 t2 = *(const float4*)&Bs[kk*132 + tx*8];
            float4 t3 = *(const float4*)&Bs[kk*132 + tx*8 + 4];
            a[0]=t0.x;a[1]=t0.y;a[2]=t0.z;a[3]=t0.w;a[4]=t1.x;a[5]=t1.y;a[6]=t1.z;a[7]=t1.w;
            b[0]=t2.x;b[1]=t2.y;b[2]=t2.z;b[3]=t2.w;b[4]=t3.x;b[5]=t3.y;b[6]=t3.z;b[7]=t3.w;
            #pragma unroll
            for (int i = 0; i < 8; i++)
                #pragma unroll
                for (int j = 0; j < 8; j++) acc[i][j] = fmaf(a[i], b[j], acc[i][j]);
        }
    }
    float bb[8];
    #pragma unroll
    for (int j = 0; j < 8; j++) {
        int n = n0 + tx*8 + j;
        bb[j] = bih[blockIdx.z*1024 + n] + bhh[blockIdx.z*1024 + n];
    }
    #pragma unroll
    for (int i = 0; i < 8; i++) {
        float* crow = C + (m0 + ty*8 + i)*1024 + n0 + tx*8;
        #pragma unroll
        for (int j = 0; j < 8; j++) crow[j] = acc[i][j] + bb[j];
    }
}

// ================= LSTM recurrence step =================
// grid (30 rowblocks, 4 hidden-slices, 2 dirs), 256 threads.
__global__ __launch_bounds__(256) void lstm_step(
    int layer, int s, const float* __restrict__ Whh, const int* __restrict__ lens)
{
    const int r0  = blockIdx.x * 8;
    const int j0  = blockIdx.y * 64;
    const int dir = blockIdx.z;
    const int p   = s & 1;
    const float* pre = g_pre + dir * (MROWS * 1024);
    float* outb = layer ? g_out1 : g_out0;
    const int t = dir ? (31 - s) : s;

    __shared__ float hs[8][256];
    __shared__ float zs[4][64][9];
    const int tid = threadIdx.x;

    if (s == 0) {
        for (int i = tid; i < 2048; i += 256) hs[i >> 8][i & 255] = 0.f;
    } else {
        const float* hp = g_h[p][dir];
        for (int i = tid; i < 2048; i += 256) {
            int r = i >> 8, k = i & 255;
            hs[r][k] = hp[(r0 + r)*256 + k];
        }
    }
    __syncthreads();

    const int jl = tid & 63, gt = tid >> 6;
    const int gidx = gt*256 + j0 + jl;
    float acc[8];
    #pragma unroll
    for (int r = 0; r < 8; r++)
        acc[r] = pre[((r0 + r)*32 + t)*1024 + gidx];
    const float* wrow = Whh + dir*1024*256 + gidx*256;
    for (int k = 0; k < 256; k += 4) {
        float4 w = *(const float4*)(wrow + k);
        #pragma unroll
        for (int r = 0; r < 8; r++) {
            float4 hv = *(const float4*)&hs[r][k];
            acc[r] += w.x*hv.x + w.y*hv.y + w.z*hv.z + w.w*hv.w;
        }
    }
    #pragma unroll
    for (int r = 0; r < 8; r++) zs[gt][jl][r] = acc[r];
    __syncthreads();

    const int jl2 = tid & 63, rg = tid >> 6;
    float* hn = g_h[p ^ 1][dir];
    float* cS = g_c[dir];
    #pragma unroll
    for (int q = 0; q < 2; q++) {
        int rr = rg + q*4;
        int row = r0 + rr, j = j0 + jl2;
        float zi = zs[0][jl2][rr], zf = zs[1][jl2][rr];
        float zg = zs[2][jl2][rr], zo = zs[3][jl2][rr];
        float c_old = (s == 0) ? 0.f : cS[row*256 + j];
        float h_old = hs[rr][j];
        bool m = t < lens[row];
        float si = 1.f / (1.f + expf(-zi));
        float sf = 1.f / (1.f + expf(-zf));
        float so = 1.f / (1.f + expf(-zo));
        float cn = sf*c_old + si*tanhf(zg);
        float hv = so*tanhf(cn);
        cS[row*256 + j] = m ? cn : c_old;
        hn[row*256 + j] = m ? hv : h_old;
        outb[(row*32 + t)*512 + dir*256 + j] = m ? hv : 0.f;
    }
}

// ================= masked mean over time =================
__global__ void avg_kernel(const int* __restrict__ lens)
{
    const int row = blockIdx.x;   // 240
    const int k = threadIdx.x;    // 512
    float s = 0.f;
    for (int t = 0; t < 32; t++) s += g_out1[(row*32 + t)*512 + k];
    g_avg[row*512 + k] = s / (float)lens[row];
}

// ================= logits + per-video max + sigmoid =================
__global__ void final_kernel(const float* __restrict__ lw, const float* __restrict__ lb,
                             float* __restrict__ out)
{
    const int v = blockIdx.x / NCLS, c = blockIdx.x % NCLS;
    const int tid = threadIdx.x;  // 64
    float lg = -1e30f;
    if (tid < 60) {
        int rec = v*60 + tid;
        int sg = tid / 15, pp = tid % 15;
        int f = v*64 + sg*16 + pp;
        const float* av = g_avg + rec*512;
        const float* w  = lw + c*6784 + 6272;
        float dot = 0.f;
        #pragma unroll 4
        for (int k = 0; k < 512; k++) dot += av[k]*w[k];
        lg = 0.5f*(g_fdot[f*NCLS + c] + g_fdot[(f+1)*NCLS + c]) + dot + lb[c];
    }
    for (int off = 16; off; off >>= 1)
        lg = fmaxf(lg, __shfl_xor_sync(0xffffffffu, lg, off));
    __shared__ float red[2];
    if ((tid & 31) == 0) red[tid >> 5] = lg;
    __syncthreads();
    if (tid == 0) {
        float m = fmaxf(red[0], red[1]);
        out[v*NCLS + c] = 1.f / (1.f + expf(-m));
    }
}

// ================= launch =================
extern "C" void kernel_launch(void* const* d_in, const int* in_sizes, int n_in,
                              void* d_out, int out_size)
{
    const float* img  = (const float*)d_in[0];
    const int*   txt  = (const int*)d_in[1];
    const int*   lens = (const int*)d_in[2];
    const float* emb  = (const float*)d_in[7];
    const float* Wih0 = (const float*)d_in[8];
    const float* Whh0 = (const float*)d_in[9];
    const float* bih0 = (const float*)d_in[10];
    const float* bhh0 = (const float*)d_in[11];
    const float* Wih1 = (const float*)d_in[12];
    const float* Whh1 = (const float*)d_in[13];
    const float* bih1 = (const float*)d_in[14];
    const float* bhh1 = (const float*)d_in[15];
    const float* cw   = (const float*)d_in[16];
    const float* cb   = (const float*)d_in[17];
    const float* lw   = (const float*)d_in[18];
    const float* lb   = (const float*)d_in[19];
    float* out = (float*)d_out;

    cudaFuncSetAttribute(conv_pool_kernel,
                         cudaFuncAttributeMaxDynamicSharedMemorySize, CONV_SMEM);

    conv_pool_kernel<<<dim3(14,32,8), 448, CONV_SMEM>>>(img, cw);
    fdot_kernel<<<256, 256>>>(cb, lw);
    pad_wih_kernel<<<2048, 128>>>(Wih0);
    embed_kernel<<<7680, 128>>>(txt, emb);
    gemm_kernel<<<dim3(60,8,2), 256>>>(0, (const float*)nullptr, bih0, bhh0);
    for (int s = 0; s < 32; s++)
        lstm_step<<<dim3(30,4,2), 256>>>(0, s, Whh0, lens);
    gemm_kernel<<<dim3(60,8,2), 256>>>(1, Wih1, bih1, bhh1);
    for (int s = 0; s < 32; s++)
        lstm_step<<<dim3(30,4,2), 256>>>(1, s, Whh1, lens);
    avg_kernel<<<240, 512>>>(lens);
    final_kernel<<<80, 64>>>(lw, lb, out);
}

// round 4
// speedup vs baseline: 1.4888x; 1.4888x over previous
#include <cuda_runtime.h>
#include <math.h>

// ---------------- problem constants ----------------
#define NVID  4
#define FPV   64
#define TOTF  256
#define NRECS 240
#define TTXT  32
#define EPAD  304      // 300 padded to 304 for float4
#define HIDN  256
#define NCLS  20
#define OCC   32
#define MROWS 7680     // 240*32

typedef unsigned long long u64;

// packed f32x2 helpers (Blackwell sm_103a): bit-exact vs two scalar fmaf
__device__ __forceinline__ u64 pk2(float lo, float hi) {
    u64 r; asm("mov.b64 %0, {%1, %2};" : "=l"(r) : "f"(lo), "f"(hi)); return r;
}
__device__ __forceinline__ void fma2(u64& d, u64 a, u64 b) {
    asm("fma.rn.f32x2 %0, %1, %2, %0;" : "+l"(d) : "l"(a), "l"(b));
}
__device__ __forceinline__ float2 upk2(u64 v) {
    float2 f; asm("mov.b64 {%0, %1}, %2;" : "=f"(f.x), "=f"(f.y) : "l"(v)); return f;
}

// ---------------- device-global scratch (allocation-free rule) ----------------
__device__ float g_part[NVID*OCC*FPV*196];   // conv + HW-pool result [v][oc][d][14][14]
__device__ float g_fdot[TOTF*NCLS];          // per-frame pooled-feature . lin_w
__device__ float g_x0[MROWS*EPAD];           // embedded text, K padded
__device__ float g_wpad[2*1024*EPAD];        // Wih_l0 padded 300->304
__device__ float g_pre[2*MROWS*1024];        // input-proj gates per dir (reused per layer)
__device__ float g_out0[MROWS*512];          // layer0 output [row][t][512]
__device__ float g_out1[MROWS*512];          // layer1 output
__device__ float g_h[2][2][NRECS*HIDN];      // [parity][dir][row*256+j]
__device__ float g_c[2][NRECS*HIDN];         // [dir]
__device__ float g_avg[NRECS*512];

// ================= Conv3D + HW max-pool (fused) =================
// grid (14 ph, 32 dpair, v*2+half), 448 threads.
#define PATCH_ROW 122
#define PATCH_SZ  (3*4*21*PATCH_ROW)
#define WSZ       (32*441)
#define CONV_SMEM ((PATCH_SZ + WSZ) * 4)

__global__ __launch_bounds__(448,1) void conv_pool_kernel(
    const float* __restrict__ img, const float* __restrict__ cw)
{
    extern __shared__ float sh[];
    float* patch = sh;
    float* ws    = sh + PATCH_SZ;
    const int ph = blockIdx.x;
    const int d0 = blockIdx.y * 2;
    const int v  = blockIdx.z >> 1, half = blockIdx.z & 1;
    const int tid = threadIdx.x;

    for (int i = tid; i < WSZ; i += 448) ws[i] = cw[i];

    const int NLOAD = 3*4*21*117;
    for (int i = tid; i < NLOAD; i += 448) {
        int c  = i % 117; int rr = i / 117;
        int r  = rr % 21; int dds = (rr / 21) & 3; int ci = rr / 84;
        int iw = 112*half - 3 + c;
        int ih = 16*ph    - 3 + r;
        int dd = d0 - 1 + dds;
        float val = 0.f;
        if ((unsigned)dd < 64u && (unsigned)ih < 224u && (unsigned)iw < 224u)
            val = img[(((v*64 + dd)*3 + ci)*224 + ih)*224 + iw];
        patch[((ci*4 + dds)*21 + r)*PATCH_ROW + (c & 1)*61 + (c >> 1)] = val;
    }
    __syncthreads();

    const int dloc = tid / 224; const int rem = tid % 224;
    const int pwl  = rem >> 5;  const int lane = rem & 31;
    const int ocg  = lane >> 3; const int hh  = lane & 7;

    u64 accp[8][4];
    #pragma unroll
    for (int r = 0; r < 8; r++)
        #pragma unroll
        for (int p = 0; p < 4; p++) accp[r][p] = 0ull;

    for (int ci = 0; ci < 3; ci++)
    for (int kd = 0; kd < 3; kd++)
    #pragma unroll 1
    for (int kh = 0; kh < 7; kh++) {
        const float* prow = &patch[((ci*4 + dloc + kd)*21 + 2*hh + kh)*PATCH_ROW];
        const float* wrow = &ws[(ocg*8)*441 + ci*147 + kd*49 + kh*7];
        #pragma unroll
        for (int kw = 0; kw < 7; kw++) {
            const float* xp = prow + (kw & 1)*61 + 8*pwl + (kw >> 1);
            u64 xv2[4];
            #pragma unroll
            for (int p = 0; p < 4; p++) xv2[p] = pk2(xp[2*p], xp[2*p+1]);
            #pragma unroll
            for (int r = 0; r < 8; r++) {
                float wv = wrow[r*441 + kw];
                u64 w2 = pk2(wv, wv);
                #pragma unroll
                for (int p = 0; p < 4; p++) fma2(accp[r][p], w2, xv2[p]);
            }
        }
    }

    const int d  = d0 + dloc;
    const int pw = half*7 + pwl;
    #pragma unroll
    for (int r = 0; r < 8; r++) {
        float2 f0 = upk2(accp[r][0]);
        float mx = fmaxf(f0.x, f0.y);
        #pragma unroll
        for (int p = 1; p < 4; p++) {
            float2 fp = upk2(accp[r][p]);
            mx = fmaxf(mx, fmaxf(fp.x, fp.y));
        }
        mx = fmaxf(mx, __shfl_xor_sync(0xffffffffu, mx, 4));
        mx = fmaxf(mx, __shfl_xor_sync(0xffffffffu, mx, 2));
        mx = fmaxf(mx, __shfl_xor_sync(0xffffffffu, mx, 1));
        if (hh == 0) {
            int oc = ocg*8 + r;
            g_part[(((v*OCC + oc)*FPV + d)*14 + ph)*14 + pw] = mx;
        }
    }
}

// ================= D-pool + (pooled features) . lin_w -> g_fdot =================
__global__ void fdot_kernel(const float* __restrict__ cb, const float* __restrict__ lw)
{
    const int f = blockIdx.x;            // 256
    const int v = f >> 6, d = f & 63;
    const int tid = threadIdx.x;         // 256
    float acc[NCLS];
    #pragma unroll
    for (int c = 0; c < NCLS; c++) acc[c] = 0.f;

    for (int k = tid; k < 6272; k += 256) {
        int oc = k / 196; int rem2 = k % 196;
        const float* base = g_part + (v*OCC + oc)*FPV*196 + rem2;
        float val = base[d*196];
        if (d > 0)  val = fmaxf(val, base[(d-1)*196]);
        if (d < 63) val = fmaxf(val, base[(d+1)*196]);
        val += cb[oc];
        #pragma unroll
        for (int c = 0; c < NCLS; c++) acc[c] = fmaf(val, lw[c*6784 + k], acc[c]);
    }
    #pragma unroll
    for (int c = 0; c < NCLS; c++)
        for (int off = 16; off; off >>= 1)
            acc[c] += __shfl_xor_sync(0xffffffffu, acc[c], off);

    __shared__ float red[8][NCLS];
    const int wid = tid >> 5, lane = tid & 31;
    if (lane == 0)
        #pragma unroll
        for (int c = 0; c < NCLS; c++) red[wid][c] = acc[c];
    __syncthreads();
    if (tid < NCLS) {
        float s = 0.f;
        #pragma unroll
        for (int w = 0; w < 8; w++) s += red[w][tid];
        g_fdot[f*NCLS + tid] = s;
    }
}

// ================= Embedding gather (pad K to 304) =================
__global__ void embed_kernel(const int* __restrict__ txt, const float* __restrict__ emb)
{
    const int m = blockIdx.x;            // 7680 = row*32 + t
    const int tok = txt[m];
    const float* e = emb + (long long)tok * 300;
    for (int k = threadIdx.x; k < EPAD; k += 128)
        g_x0[m*EPAD + k] = (k < 300) ? e[k] : 0.f;
}

__global__ void pad_wih_kernel(const float* __restrict__ Wih0)
{
    const int row = blockIdx.x;          // 2048 = dir*1024 + gate
    const float* src = Wih0 + row * 300;
    for (int k = threadIdx.x; k < EPAD; k += 128)
        g_wpad[row*EPAD + k] = (k < 300) ? src[k] : 0.f;
}

// ================= SGEMM: pre = X @ Wih^T + bih + bhh =================
// grid (60, 8, 2 dirs), 256 threads, 128x128 tile, 8x8 per thread, f32x2.
__global__ __launch_bounds__(256,2) void gemm_kernel(
    int layer, const float* __restrict__ Bext,
    const float* __restrict__ bih, const float* __restrict__ bhh)
{
    const int K = layer ? 512 : EPAD;
    const float* A = layer ? g_out0 : g_x0;
    const float* B = (layer ? Bext : (const float*)g_wpad) + blockIdx.z * 1024 * K;
    float* C = g_pre + blockIdx.z * (MROWS * 1024);
    const int m0 = blockIdx.x * 128, n0 = blockIdx.y * 128;

    __shared__ float As[8*132];
    __shared__ float Bs[8*132];
    const int tid = threadIdx.x;
    const int lr = tid >> 1;
    const int lk = (tid & 1) * 4;
    const int ty = tid >> 4, tx = tid & 15;
    const float* Arow = A + (m0 + lr)*K + lk;
    const float* Brow = B + (n0 + lr)*K + lk;

    u64 accp[8][4];
    #pragma unroll
    for (int i = 0; i < 8; i++)
        #pragma unroll
        for (int p = 0; p < 4; p++) accp[i][p] = 0ull;

    for (int k0 = 0; k0 < K; k0 += 8) {
        float4 va = *(const float4*)(Arow + k0);
        float4 vb = *(const float4*)(Brow + k0);
        __syncthreads();
        As[(lk+0)*132 + lr] = va.x; As[(lk+1)*132 + lr] = va.y;
        As[(lk+2)*132 + lr] = va.z; As[(lk+3)*132 + lr] = va.w;
        Bs[(lk+0)*132 + lr] = vb.x; Bs[(lk+1)*132 + lr] = vb.y;
        Bs[(lk+2)*132 + lr] = vb.z; Bs[(lk+3)*132 + lr] = vb.w;
        __syncthreads();
        #pragma unroll
        for (int kk = 0; kk < 8; kk++) {
            float a[8];
            float4 t0 = *(const float4*)&As[kk*132 + ty*8];
            float4 t1 = *(const float4*)&As[kk*132 + ty*8 + 4];
            float4 t2 = *(const float4*)&Bs[kk*132 + tx*8];
            float4 t3 = *(const float4*)&Bs[kk*132 + tx*8 + 4];
            a[0]=t0.x;a[1]=t0.y;a[2]=t0.z;a[3]=t0.w;a[4]=t1.x;a[5]=t1.y;a[6]=t1.z;a[7]=t1.w;
            u64 bp[4];
            bp[0] = pk2(t2.x, t2.y); bp[1] = pk2(t2.z, t2.w);
            bp[2] = pk2(t3.x, t3.y); bp[3] = pk2(t3.z, t3.w);
            #pragma unroll
            for (int i = 0; i < 8; i++) {
                u64 a2 = pk2(a[i], a[i]);
                #pragma unroll
                for (int p = 0; p < 4; p++) fma2(accp[i][p], a2, bp[p]);
            }
        }
    }
    float bb[8];
    #pragma unroll
    for (int j = 0; j < 8; j++) {
        int n = n0 + tx*8 + j;
        bb[j] = bih[blockIdx.z*1024 + n] + bhh[blockIdx.z*1024 + n];
    }
    #pragma unroll
    for (int i = 0; i < 8; i++) {
        float* crow = C + (m0 + ty*8 + i)*1024 + n0 + tx*8;
        #pragma unroll
        for (int p = 0; p < 4; p++) {
            float2 f = upk2(accp[i][p]);
            crow[2*p]   = f.x + bb[2*p];
            crow[2*p+1] = f.y + bb[2*p+1];
        }
    }
}

// ================= LSTM recurrence step (f32x2, transposed h in smem) ========
// grid (30 rowblocks, 4 hidden-slices, 2 dirs), 256 threads.
__global__ __launch_bounds__(256) void lstm_step(
    int layer, int s, const float* __restrict__ Whh, const int* __restrict__ lens)
{
    const int r0  = blockIdx.x * 8;
    const int j0  = blockIdx.y * 64;
    const int dir = blockIdx.z;
    const int p   = s & 1;
    const float* pre = g_pre + dir * (MROWS * 1024);
    float* outb = layer ? g_out1 : g_out0;
    const int t = dir ? (31 - s) : s;

    __shared__ float hs2[256][10];       // [k][r] transposed, pad-10 (8B-aligned pairs)
    __shared__ float zs[4][64][9];
    const int tid = threadIdx.x;

    if (s == 0) {
        for (int i = tid; i < 2048; i += 256) hs2[i & 255][i >> 8] = 0.f;
    } else {
        const float* hp = g_h[p][dir];
        for (int i = tid; i < 2048; i += 256) {
            int r = i >> 8, k = i & 255;
            hs2[k][r] = hp[(r0 + r)*256 + k];
        }
    }
    __syncthreads();

    const int jl = tid & 63, gt = tid >> 6;
    const int gidx = gt*256 + j0 + jl;
    u64 accp[4];
    #pragma unroll
    for (int q = 0; q < 4; q++)
        accp[q] = pk2(pre[((r0 + 2*q)*32 + t)*1024 + gidx],
                      pre[((r0 + 2*q + 1)*32 + t)*1024 + gidx]);

    const float* wrow = Whh + dir*1024*256 + gidx*256;
    for (int k0 = 0; k0 < 256; k0 += 4) {
        float4 w = *(const float4*)(wrow + k0);
        float wk[4] = {w.x, w.y, w.z, w.w};
        #pragma unroll
        for (int kk = 0; kk < 4; kk++) {
            u64 w2 = pk2(wk[kk], wk[kk]);
            const u64* hrow = (const u64*)&hs2[k0 + kk][0];
            #pragma unroll
            for (int q = 0; q < 4; q++) fma2(accp[q], w2, hrow[q]);
        }
    }
    #pragma unroll
    for (int q = 0; q < 4; q++) {
        float2 f = upk2(accp[q]);
        zs[gt][jl][2*q]   = f.x;
        zs[gt][jl][2*q+1] = f.y;
    }
    __syncthreads();

    const int jl2 = tid & 63, rg = tid >> 6;
    float* hn = g_h[p ^ 1][dir];
    float* cS = g_c[dir];
    #pragma unroll
    for (int q = 0; q < 2; q++) {
        int rr = rg + q*4;
        int row = r0 + rr, j = j0 + jl2;
        float zi = zs[0][jl2][rr], zf = zs[1][jl2][rr];
        float zg = zs[2][jl2][rr], zo = zs[3][jl2][rr];
        float c_old = (s == 0) ? 0.f : cS[row*256 + j];
        float h_old = hs2[j][rr];
        bool m = t < lens[row];
        float si = 1.f / (1.f + expf(-zi));
        float sf = 1.f / (1.f + expf(-zf));
        float so = 1.f / (1.f + expf(-zo));
        float cn = sf*c_old + si*tanhf(zg);
        float hv = so*tanhf(cn);
        cS[row*256 + j] = m ? cn : c_old;
        hn[row*256 + j] = m ? hv : h_old;
        outb[(row*32 + t)*512 + dir*256 + j] = m ? hv : 0.f;
    }
}

// ================= masked mean over time =================
__global__ void avg_kernel(const int* __restrict__ lens)
{
    const int row = blockIdx.x;   // 240
    const int k = threadIdx.x;    // 512
    float s = 0.f;
    for (int t = 0; t < 32; t++) s += g_out1[(row*32 + t)*512 + k];
    g_avg[row*512 + k] = s / (float)lens[row];
}

// ================= logits + per-video max + sigmoid =================
__global__ void final_kernel(const float* __restrict__ lw, const float* __restrict__ lb,
                             float* __restrict__ out)
{
    const int v = blockIdx.x / NCLS, c = blockIdx.x % NCLS;
    const int tid = threadIdx.x;  // 64
    float lg = -1e30f;
    if (tid < 60) {
        int rec = v*60 + tid;
        int sg = tid / 15, pp = tid % 15;
        int f = v*64 + sg*16 + pp;
        const float* av = g_avg + rec*512;
        const float* w  = lw + c*6784 + 6272;
        float dot = 0.f;
        #pragma unroll 4
        for (int k = 0; k < 512; k++) dot += av[k]*w[k];
        lg = 0.5f*(g_fdot[f*NCLS + c] + g_fdot[(f+1)*NCLS + c]) + dot + lb[c];
    }
    for (int off = 16; off; off >>= 1)
        lg = fmaxf(lg, __shfl_xor_sync(0xffffffffu, lg, off));
    __shared__ float red[2];
    if ((tid & 31) == 0) red[tid >> 5] = lg;
    __syncthreads();
    if (tid == 0) {
        float m = fmaxf(red[0], red[1]);
        out[v*NCLS + c] = 1.f / (1.f + expf(-m));
    }
}

// ================= launch =================
// Ordering puts conv_pool at launch #6 so ncu (-s 5 -c 1) profiles IT next round.
extern "C" void kernel_launch(void* const* d_in, const int* in_sizes, int n_in,
                              void* d_out, int out_size)
{
    const float* img  = (const float*)d_in[0];
    const int*   txt  = (const int*)d_in[1];
    const int*   lens = (const int*)d_in[2];
    const float* emb  = (const float*)d_in[7];
    const float* Wih0 = (const float*)d_in[8];
    const float* Whh0 = (const float*)d_in[9];
    const float* bih0 = (const float*)d_in[10];
    const float* bhh0 = (const float*)d_in[11];
    const float* Wih1 = (const float*)d_in[12];
    const float* Whh1 = (const float*)d_in[13];
    const float* bih1 = (const float*)d_in[14];
    const float* bhh1 = (const float*)d_in[15];
    const float* cw   = (const float*)d_in[16];
    const float* cb   = (const float*)d_in[17];
    const float* lw   = (const float*)d_in[18];
    const float* lb   = (const float*)d_in[19];
    float* out = (float*)d_out;

    cudaFuncSetAttribute(conv_pool_kernel,
                         cudaFuncAttributeMaxDynamicSharedMemorySize, CONV_SMEM);

    // text branch first (independent of conv) so conv_pool is launch #6
    pad_wih_kernel<<<2048, 128>>>(Wih0);                       // 1
    embed_kernel<<<7680, 128>>>(txt, emb);                     // 2
    gemm_kernel<<<dim3(60,8,2), 256>>>(0, (const float*)nullptr, bih0, bhh0); // 3
    lstm_step<<<dim3(30,4,2), 256>>>(0, 0, Whh0, lens);        // 4
    lstm_step<<<dim3(30,4,2), 256>>>(0, 1, Whh0, lens);        // 5
    conv_pool_kernel<<<dim3(14,32,8), 448, CONV_SMEM>>>(img, cw); // 6 <- profiled
    for (int s = 2; s < 32; s++)
        lstm_step<<<dim3(30,4,2), 256>>>(0, s, Whh0, lens);
    fdot_kernel<<<256, 256>>>(cb, lw);
    gemm_kernel<<<dim3(60,8,2), 256>>>(1, Wih1, bih1, bhh1);
    for (int s = 0; s < 32; s++)
        lstm_step<<<dim3(30,4,2), 256>>>(1, s, Whh1, lens);
    avg_kernel<<<240, 512>>>(lens);
    final_kernel<<<80, 64>>>(lw, lb, out);
}

// round 6
// speedup vs baseline: 1.4997x; 1.0073x over previous
#include <cuda_runtime.h>
#include <math.h>

// ---------------- problem constants ----------------
#define NVID  4
#define FPV   64
#define TOTF  256
#define NRECS 240
#define TTXT  32
#define EPAD  304      // 300 padded to 304 for float4
#define HIDN  256
#define NCLS  20
#define OCC   32
#define MROWS 7680     // 240*32

typedef unsigned long long u64;

// packed f32x2 helpers (Blackwell sm_103a): bit-exact vs two scalar fmaf
__device__ __forceinline__ u64 pk2(float lo, float hi) {
    u64 r; asm("mov.b64 %0, {%1, %2};" : "=l"(r) : "f"(lo), "f"(hi)); return r;
}
__device__ __forceinline__ void fma2(u64& d, u64 a, u64 b) {
    asm("fma.rn.f32x2 %0, %1, %2, %0;" : "+l"(d) : "l"(a), "l"(b));
}
__device__ __forceinline__ float2 upk2(u64 v) {
    float2 f; asm("mov.b64 {%0, %1}, %2;" : "=f"(f.x), "=f"(f.y) : "l"(v)); return f;
}

// ---------------- device-global scratch (allocation-free rule) ----------------
__device__ float g_part[NVID*OCC*FPV*196];   // conv + HW-pool result [v][oc][d][14][14]
__device__ float g_fdot[TOTF*NCLS];          // per-frame pooled-feature . lin_w
__device__ float g_x0[MROWS*EPAD];           // embedded text, K padded
__device__ float g_wpad[2*1024*EPAD];        // Wih_l0 padded 300->304
__device__ float g_pre[2*MROWS*1024];        // input-proj gates per dir (reused per layer)
__device__ float g_out0[MROWS*512];          // layer0 output [row][t][512]
__device__ float g_out1[MROWS*512];          // layer1 output
__device__ float g_h[2][2][NRECS*HIDN];      // [parity][dir][row*256+j]
__device__ float g_c[2][NRECS*HIDN];         // [dir]
__device__ float g_avg[NRECS*512];

// ================= Conv3D + HW max-pool (fused) =================
// grid (14 ph, 32 dpair, v*2+half), 448 threads.
#define PATCH_ROW 122
#define PATCH_SZ  (3*4*21*PATCH_ROW)
#define WSZ       (32*441)
#define CONV_SMEM ((PATCH_SZ + WSZ) * 4)

__global__ __launch_bounds__(448,1) void conv_pool_kernel(
    const float* __restrict__ img, const float* __restrict__ cw)
{
    extern __shared__ float sh[];
    float* patch = sh;
    float* ws    = sh + PATCH_SZ;
    const int ph = blockIdx.x;
    const int d0 = blockIdx.y * 2;
    const int v  = blockIdx.z >> 1, half = blockIdx.z & 1;
    const int tid = threadIdx.x;

    for (int i = tid; i < WSZ; i += 448) ws[i] = cw[i];

    const int NLOAD = 3*4*21*117;
    for (int i = tid; i < NLOAD; i += 448) {
        int c  = i % 117; int rr = i / 117;
        int r  = rr % 21; int dds = (rr / 21) & 3; int ci = rr / 84;
        int iw = 112*half - 3 + c;
        int ih = 16*ph    - 3 + r;
        int dd = d0 - 1 + dds;
        float val = 0.f;
        if ((unsigned)dd < 64u && (unsigned)ih < 224u && (unsigned)iw < 224u)
            val = img[(((v*64 + dd)*3 + ci)*224 + ih)*224 + iw];
        patch[((ci*4 + dds)*21 + r)*PATCH_ROW + (c & 1)*61 + (c >> 1)] = val;
    }
    __syncthreads();

    const int dloc = tid / 224; const int rem = tid % 224;
    const int pwl  = rem >> 5;  const int lane = rem & 31;
    const int ocg  = lane >> 3; const int hh  = lane & 7;

    u64 accp[8][4];
    #pragma unroll
    for (int r = 0; r < 8; r++)
        #pragma unroll
        for (int p = 0; p < 4; p++) accp[r][p] = 0ull;

    for (int ci = 0; ci < 3; ci++)
    for (int kd = 0; kd < 3; kd++)
    #pragma unroll 1
    for (int kh = 0; kh < 7; kh++) {
        const float* prow = &patch[((ci*4 + dloc + kd)*21 + 2*hh + kh)*PATCH_ROW];
        const float* wrow = &ws[(ocg*8)*441 + ci*147 + kd*49 + kh*7];
        #pragma unroll
        for (int kw = 0; kw < 7; kw++) {
            const float* xp = prow + (kw & 1)*61 + 8*pwl + (kw >> 1);
            u64 xv2[4];
            #pragma unroll
            for (int p = 0; p < 4; p++) xv2[p] = pk2(xp[2*p], xp[2*p+1]);
            #pragma unroll
            for (int r = 0; r < 8; r++) {
                float wv = wrow[r*441 + kw];
                u64 w2 = pk2(wv, wv);
                #pragma unroll
                for (int p = 0; p < 4; p++) fma2(accp[r][p], w2, xv2[p]);
            }
        }
    }

    const int d  = d0 + dloc;
    const int pw = half*7 + pwl;
    #pragma unroll
    for (int r = 0; r < 8; r++) {
        float2 f0 = upk2(accp[r][0]);
        float mx = fmaxf(f0.x, f0.y);
        #pragma unroll
        for (int p = 1; p < 4; p++) {
            float2 fp = upk2(accp[r][p]);
            mx = fmaxf(mx, fmaxf(fp.x, fp.y));
        }
        mx = fmaxf(mx, __shfl_xor_sync(0xffffffffu, mx, 4));
        mx = fmaxf(mx, __shfl_xor_sync(0xffffffffu, mx, 2));
        mx = fmaxf(mx, __shfl_xor_sync(0xffffffffu, mx, 1));
        if (hh == 0) {
            int oc = ocg*8 + r;
            g_part[(((v*OCC + oc)*FPV + d)*14 + ph)*14 + pw] = mx;
        }
    }
}

// ================= D-pool + (pooled features) . lin_w -> g_fdot =================
__global__ void fdot_kernel(const float* __restrict__ cb, const float* __restrict__ lw)
{
    const int f = blockIdx.x;            // 256
    const int v = f >> 6, d = f & 63;
    const int tid = threadIdx.x;         // 256
    float acc[NCLS];
    #pragma unroll
    for (int c = 0; c < NCLS; c++) acc[c] = 0.f;

    for (int k = tid; k < 6272; k += 256) {
        int oc = k / 196; int rem2 = k % 196;
        const float* base = g_part + (v*OCC + oc)*FPV*196 + rem2;
        float val = base[d*196];
        if (d > 0)  val = fmaxf(val, base[(d-1)*196]);
        if (d < 63) val = fmaxf(val, base[(d+1)*196]);
        val += cb[oc];
        #pragma unroll
        for (int c = 0; c < NCLS; c++) acc[c] = fmaf(val, lw[c*6784 + k], acc[c]);
    }
    #pragma unroll
    for (int c = 0; c < NCLS; c++)
        for (int off = 16; off; off >>= 1)
            acc[c] += __shfl_xor_sync(0xffffffffu, acc[c], off);

    __shared__ float red[8][NCLS];
    const int wid = tid >> 5, lane = tid & 31;
    if (lane == 0)
        #pragma unroll
        for (int c = 0; c < NCLS; c++) red[wid][c] = acc[c];
    __syncthreads();
    if (tid < NCLS) {
        float s = 0.f;
        #pragma unroll
        for (int w = 0; w < 8; w++) s += red[w][tid];
        g_fdot[f*NCLS + tid] = s;
    }
}

// ================= Embedding gather (pad K to 304) =================
__global__ void embed_kernel(const int* __restrict__ txt, const float* __restrict__ emb)
{
    const int m = blockIdx.x;            // 7680 = row*32 + t
    const int tok = txt[m];
    const float* e = emb + (long long)tok * 300;
    for (int k = threadIdx.x; k < EPAD; k += 128)
        g_x0[m*EPAD + k] = (k < 300) ? e[k] : 0.f;
}

__global__ void pad_wih_kernel(const float* __restrict__ Wih0)
{
    const int row = blockIdx.x;          // 2048 = dir*1024 + gate
    const float* src = Wih0 + row * 300;
    for (int k = threadIdx.x; k < EPAD; k += 128)
        g_wpad[row*EPAD + k] = (k < 300) ? src[k] : 0.f;
}

// ================= SGEMM: pre = X @ Wih^T + bih + bhh =================
// grid (60, 8, 2 dirs), 256 threads, 128x128 tile, 8x8 per thread, f32x2.
__global__ __launch_bounds__(256,2) void gemm_kernel(
    int layer, const float* __restrict__ Bext,
    const float* __restrict__ bih, const float* __restrict__ bhh)
{
    const int K = layer ? 512 : EPAD;
    const float* A = layer ? g_out0 : g_x0;
    const float* B = (layer ? Bext : (const float*)g_wpad) + blockIdx.z * 1024 * K;
    float* C = g_pre + blockIdx.z * (MROWS * 1024);
    const int m0 = blockIdx.x * 128, n0 = blockIdx.y * 128;

    __shared__ float As[8*132];
    __shared__ float Bs[8*132];
    const int tid = threadIdx.x;
    const int lr = tid >> 1;
    const int lk = (tid & 1) * 4;
    const int ty = tid >> 4, tx = tid & 15;
    const float* Arow = A + (m0 + lr)*K + lk;
    const float* Brow = B + (n0 + lr)*K + lk;

    u64 accp[8][4];
    #pragma unroll
    for (int i = 0; i < 8; i++)
        #pragma unroll
        for (int p = 0; p < 4; p++) accp[i][p] = 0ull;

    for (int k0 = 0; k0 < K; k0 += 8) {
        float4 va = *(const float4*)(Arow + k0);
        float4 vb = *(const float4*)(Brow + k0);
        __syncthreads();
        As[(lk+0)*132 + lr] = va.x; As[(lk+1)*132 + lr] = va.y;
        As[(lk+2)*132 + lr] = va.z; As[(lk+3)*132 + lr] = va.w;
        Bs[(lk+0)*132 + lr] = vb.x; Bs[(lk+1)*132 + lr] = vb.y;
        Bs[(lk+2)*132 + lr] = vb.z; Bs[(lk+3)*132 + lr] = vb.w;
        __syncthreads();
        #pragma unroll
        for (int kk = 0; kk < 8; kk++) {
            float a[8];
            float4 t0 = *(const float4*)&As[kk*132 + ty*8];
            float4 t1 = *(const float4*)&As[kk*132 + ty*8 + 4];
            float4 t2 = *(const float4*)&Bs[kk*132 + tx*8];
            float4 t3 = *(const float4*)&Bs[kk*132 + tx*8 + 4];
            a[0]=t0.x;a[1]=t0.y;a[2]=t0.z;a[3]=t0.w;a[4]=t1.x;a[5]=t1.y;a[6]=t1.z;a[7]=t1.w;
            u64 bp[4];
            bp[0] = pk2(t2.x, t2.y); bp[1] = pk2(t2.z, t2.w);
            bp[2] = pk2(t3.x, t3.y); bp[3] = pk2(t3.z, t3.w);
            #pragma unroll
            for (int i = 0; i < 8; i++) {
                u64 a2 = pk2(a[i], a[i]);
                #pragma unroll
                for (int p = 0; p < 4; p++) fma2(accp[i][p], a2, bp[p]);
            }
        }
    }
    float bb[8];
    #pragma unroll
    for (int j = 0; j < 8; j++) {
        int n = n0 + tx*8 + j;
        bb[j] = bih[blockIdx.z*1024 + n] + bhh[blockIdx.z*1024 + n];
    }
    #pragma unroll
    for (int i = 0; i < 8; i++) {
        float* crow = C + (m0 + ty*8 + i)*1024 + n0 + tx*8;
        #pragma unroll
        for (int p = 0; p < 4; p++) {
            float2 f = upk2(accp[i][p]);
            crow[2*p]   = f.x + bb[2*p];
            crow[2*p+1] = f.y + bb[2*p+1];
        }
    }
}

// ================= LSTM recurrence step: 16 rows/CTA, f32x2 =================
// grid (15 rowblocks, 4 j-slices, 2 dirs) = 120 CTAs, 256 threads.
__global__ __launch_bounds__(256) void lstm_step(
    int layer, int s, const float* __restrict__ Whh, const int* __restrict__ lens)
{
    const int r0  = blockIdx.x * 16;
    const int j0  = blockIdx.y * 64;
    const int dir = blockIdx.z;
    const int p   = s & 1;
    const float* pre = g_pre + dir * (MROWS * 1024);
    float* outb = layer ? g_out1 : g_out0;
    const int t = dir ? (31 - s) : s;

    __shared__ float hs2[256][18];       // [k][row] transposed, pad-18 (8B-aligned pairs)
    __shared__ float zs[4][64][17];      // [gate][jl][row]
    const int tid = threadIdx.x;

    if (s == 0) {
        for (int i = tid; i < 4096; i += 256) hs2[i & 255][i >> 8] = 0.f;
    } else {
        const float* hp = g_h[p][dir];
        for (int i = tid; i < 4096; i += 256) {
            int r = i >> 8, k = i & 255;
            hs2[k][r] = hp[(r0 + r)*256 + k];
        }
    }
    __syncthreads();

    const int jl = tid & 63, gt = tid >> 6;
    const int gidx = gt*256 + j0 + jl;
    u64 accp[8];
    #pragma unroll
    for (int q = 0; q < 8; q++)
        accp[q] = pk2(pre[((r0 + 2*q)*32 + t)*1024 + gidx],
                      pre[((r0 + 2*q + 1)*32 + t)*1024 + gidx]);

    const float* wrow = Whh + dir*1024*256 + gidx*256;
    #pragma unroll 2
    for (int k0 = 0; k0 < 256; k0 += 4) {
        float4 w = *(const float4*)(wrow + k0);
        float wk[4] = {w.x, w.y, w.z, w.w};
        #pragma unroll
        for (int kk = 0; kk < 4; kk++) {
            u64 w2 = pk2(wk[kk], wk[kk]);
            const u64* hrow = (const u64*)&hs2[k0 + kk][0];
            #pragma unroll
            for (int q = 0; q < 8; q++) fma2(accp[q], w2, hrow[q]);
        }
    }
    #pragma unroll
    for (int q = 0; q < 8; q++) {
        float2 f = upk2(accp[q]);
        zs[gt][jl][2*q]   = f.x;
        zs[gt][jl][2*q+1] = f.y;
    }
    __syncthreads();

    // pointwise: 64 jl x 16 rows = 1024 cells, 4 per thread
    float* hn = g_h[p ^ 1][dir];
    float* cS = g_c[dir];
    #pragma unroll
    for (int q = 0; q < 4; q++) {
        int cell = tid + 256*q;
        int jl2 = cell & 63, rr = cell >> 6;
        int row = r0 + rr, j = j0 + jl2;
        float zi = zs[0][jl2][rr], zf = zs[1][jl2][rr];
        float zg = zs[2][jl2][rr], zo = zs[3][jl2][rr];
        float c_old = (s == 0) ? 0.f : cS[row*256 + j];
        float h_old = hs2[j][rr];
        bool m = t < lens[row];
        float si = 1.f / (1.f + expf(-zi));
        float sf = 1.f / (1.f + expf(-zf));
        float so = 1.f / (1.f + expf(-zo));
        float cn = sf*c_old + si*tanhf(zg);
        float hv = so*tanhf(cn);
        cS[row*256 + j] = m ? cn : c_old;
        hn[row*256 + j] = m ? hv : h_old;
        outb[(row*32 + t)*512 + dir*256 + j] = m ? hv : 0.f;
    }
}

// ================= masked mean over time =================
__global__ void avg_kernel(const int* __restrict__ lens)
{
    const int row = blockIdx.x;   // 240
    const int k = threadIdx.x;    // 512
    float s = 0.f;
    for (int t = 0; t < 32; t++) s += g_out1[(row*32 + t)*512 + k];
    g_avg[row*512 + k] = s / (float)lens[row];
}

// ================= logits + per-video max + sigmoid =================
__global__ void final_kernel(const float* __restrict__ lw, const float* __restrict__ lb,
                             float* __restrict__ out)
{
    const int v = blockIdx.x / NCLS, c = blockIdx.x % NCLS;
    const int tid = threadIdx.x;  // 64
    float lg = -1e30f;
    if (tid < 60) {
        int rec = v*60 + tid;
        int sg = tid / 15, pp = tid % 15;
        int f = v*64 + sg*16 + pp;
        const float* av = g_avg + rec*512;
        const float* w  = lw + c*6784 + 6272;
        float dot = 0.f;
        #pragma unroll 4
        for (int k = 0; k < 512; k++) dot += av[k]*w[k];
        lg = 0.5f*(g_fdot[f*NCLS + c] + g_fdot[(f+1)*NCLS + c]) + dot + lb[c];
    }
    for (int off = 16; off; off >>= 1)
        lg = fmaxf(lg, __shfl_xor_sync(0xffffffffu, lg, off));
    __shared__ float red[2];
    if ((tid & 31) == 0) red[tid >> 5] = lg;
    __syncthreads();
    if (tid == 0) {
        float m = fmaxf(red[0], red[1]);
        out[v*NCLS + c] = 1.f / (1.f + expf(-m));
    }
}

// ================= launch =================
// Harness prepends 2 launches; ncu -s 5 -c 1 profiles overall #6 = MY #4.
// conv_pool is my #4 this round so the conv roofline is captured.
extern "C" void kernel_launch(void* const* d_in, const int* in_sizes, int n_in,
                              void* d_out, int out_size)
{
    const float* img  = (const float*)d_in[0];
    const int*   txt  = (const int*)d_in[1];
    const int*   lens = (const int*)d_in[2];
    const float* emb  = (const float*)d_in[7];
    const float* Wih0 = (const float*)d_in[8];
    const float* Whh0 = (const float*)d_in[9];
    const float* bih0 = (const float*)d_in[10];
    const float* bhh0 = (const float*)d_in[11];
    const float* Wih1 = (const float*)d_in[12];
    const float* Whh1 = (const float*)d_in[13];
    const float* bih1 = (const float*)d_in[14];
    const float* bhh1 = (const float*)d_in[15];
    const float* cw   = (const float*)d_in[16];
    const float* cb   = (const float*)d_in[17];
    const float* lw   = (const float*)d_in[18];
    const float* lb   = (const float*)d_in[19];
    float* out = (float*)d_out;

    cudaFuncSetAttribute(conv_pool_kernel,
                         cudaFuncAttributeMaxDynamicSharedMemorySize, CONV_SMEM);

    pad_wih_kernel<<<2048, 128>>>(Wih0);                          // my #1
    embed_kernel<<<7680, 128>>>(txt, emb);                        // my #2
    gemm_kernel<<<dim3(60,8,2), 256>>>(0, (const float*)nullptr, bih0, bhh0); // my #3
    conv_pool_kernel<<<dim3(14,32,8), 448, CONV_SMEM>>>(img, cw); // my #4 <- profiled
    for (int s = 0; s < 32; s++)
        lstm_step<<<dim3(15,4,2), 256>>>(0, s, Whh0, lens);
    fdot_kernel<<<256, 256>>>(cb, lw);
    gemm_kernel<<<dim3(60,8,2), 256>>>(1, Wih1, bih1, bhh1);
    for (int s = 0; s < 32; s++)
        lstm_step<<<dim3(15,4,2), 256>>>(1, s, Whh1, lens);
    avg_kernel<<<240, 512>>>(lens);
    final_kernel<<<80, 64>>>(lw, lb, out);
}

// round 7
// speedup vs baseline: 1.6428x; 1.0954x over previous
#include <cuda_runtime.h>
#include <math.h>

// ---------------- problem constants ----------------
#define NVID  4
#define FPV   64
#define TOTF  256
#define NRECS 240
#define TTXT  32
#define EPAD  304      // 300 padded to 304 for float4
#define HIDN  256
#define NCLS  20
#define OCC   32
#define MROWS 7680     // 240*32

typedef unsigned long long u64;

// packed f32x2 helpers (Blackwell sm_103a): bit-exact vs two scalar fmaf
__device__ __forceinline__ u64 pk2(float lo, float hi) {
    u64 r; asm("mov.b64 %0, {%1, %2};" : "=l"(r) : "f"(lo), "f"(hi)); return r;
}
__device__ __forceinline__ void fma2(u64& d, u64 a, u64 b) {
    asm("fma.rn.f32x2 %0, %1, %2, %0;" : "+l"(d) : "l"(a), "l"(b));
}
__device__ __forceinline__ float2 upk2(u64 v) {
    float2 f; asm("mov.b64 {%0, %1}, %2;" : "=f"(f.x), "=f"(f.y) : "l"(v)); return f;
}
// pair (lo.y, hi.x) -> one MOV64
__device__ __forceinline__ u64 shift_pair(u64 lo, u64 hi) {
    float2 a = upk2(lo), b = upk2(hi);
    return pk2(a.y, b.x);
}

// ---------------- device-global scratch (allocation-free rule) ----------------
__device__ float g_part[NVID*OCC*FPV*196];   // conv + HW-pool result [v][oc][d][14][14]
__device__ float g_fdot[TOTF*NCLS];          // per-frame pooled-feature . lin_w
__device__ float g_x0[MROWS*EPAD];           // embedded text, K padded
__device__ float g_wpad[2*1024*EPAD];        // Wih_l0 padded 300->304
__device__ float g_pre[2*MROWS*1024];        // input-proj gates per dir
__device__ float g_out0[MROWS*512];          // layer0 output [row][t][512]
__device__ float g_out1[MROWS*512];          // layer1 output
__device__ float g_h[2][2][NRECS*HIDN];      // [parity][dir][row*256+j]
__device__ float g_avg[NRECS*512];
__device__ unsigned g_sync[2][15];           // lstm cross-CTA barrier counters

// ================= Conv3D + HW max-pool (fused, per-ci staged) =================
// grid (14 ph, 32 dpair, v*2+half), 448 threads.
// Patch row: 124 floats; even-parity cols at [0..61], odd at [62..123] (8B aligned).
#define PROW 124
#define PATCH_CI (4*21*PROW)                  // 10416 floats per ci stage
#define WDUP_N (32*441)                       // 14112 duplicated weight pairs
#define CONV_SMEM (2*PATCH_CI*4 + WDUP_N*8)   // 83328 + 112896 = 196224 B

__device__ __forceinline__ void load_patch(
    float* dst, int ci, const float* __restrict__ img,
    int v, int d0, int ph, int half, int tid)
{
    const int NL = 4*21*117;
    for (int i = tid; i < NL; i += 448) {
        int c  = i % 117; int rr = i / 117;
        int r  = rr % 21; int dds = rr / 21;
        int iw = 112*half - 3 + c;
        int ih = 16*ph    - 3 + r;
        int dd = d0 - 1 + dds;
        float val = 0.f;
        if ((unsigned)dd < 64u && (unsigned)ih < 224u && (unsigned)iw < 224u)
            val = img[(((v*64 + dd)*3 + ci)*224 + ih)*224 + iw];
        dst[(dds*21 + r)*PROW + (c & 1)*62 + (c >> 1)] = val;
    }
}

__global__ __launch_bounds__(448,1) void conv_pool_kernel(
    const float* __restrict__ img, const float* __restrict__ cw)
{
    extern __shared__ float sh[];
    float* pa = sh;
    float* pb = sh + PATCH_CI;
    u64*   wd = (u64*)(sh + 2*PATCH_CI);
    const int ph = blockIdx.x;
    const int d0 = blockIdx.y * 2;
    const int v  = blockIdx.z >> 1, half = blockIdx.z & 1;
    const int tid = threadIdx.x;

    // duplicate weights into smem as (w,w) u64 pairs, layout [oc][441]
    for (int i = tid; i < WDUP_N; i += 448) {
        float w = cw[i];
        wd[i] = pk2(w, w);
    }
    load_patch(pa, 0, img, v, d0, ph, half, tid);
    __syncthreads();

    const int dloc = tid / 224; const int rem = tid % 224;
    const int pwl  = rem >> 5;  const int lane = rem & 31;
    const int ocg  = lane >> 3; const int hh  = lane & 7;

    u64 acc[8][4];
    #pragma unroll
    for (int r = 0; r < 8; r++)
        #pragma unroll
        for (int p = 0; p < 4; p++) acc[r][p] = 0ull;

    for (int ci = 0; ci < 3; ci++) {
        float* cur = (ci & 1) ? pb : pa;
        float* nxt = (ci & 1) ? pa : pb;
        if (ci < 2) load_patch(nxt, ci + 1, img, v, d0, ph, half, tid);

        for (int kd = 0; kd < 3; kd++)
        #pragma unroll 1
        for (int kh = 0; kh < 7; kh++) {
            const float* rowb = cur + ((dloc + kd)*21 + 2*hh + kh)*PROW;
            const u64* pe = (const u64*)(rowb + 8*pwl);
            const u64* po = (const u64*)(rowb + 62 + 8*pwl);
            u64 ev[6], od[6];
            #pragma unroll
            for (int q = 0; q < 6; q++) { ev[q] = pe[q]; od[q] = po[q]; }
            const u64* wk = wd + (ocg*8)*441 + ci*147 + kd*49 + kh*7;
            #pragma unroll
            for (int kw = 0; kw < 7; kw++) {
                const int s  = kw >> 1;      // shift within parity row
                const int i0 = s >> 1;
                u64 xp2[4];
                #pragma unroll
                for (int t2 = 0; t2 < 4; t2++) {
                    if (kw & 1)
                        xp2[t2] = (s & 1) ? shift_pair(od[i0 + t2], od[i0 + t2 + 1])
                                          : od[i0 + t2];
                    else
                        xp2[t2] = (s & 1) ? shift_pair(ev[i0 + t2], ev[i0 + t2 + 1])
                                          : ev[i0 + t2];
                }
                #pragma unroll
                for (int r = 0; r < 8; r++) {
                    u64 w2 = wk[r*441 + kw];
                    #pragma unroll
                    for (int p = 0; p < 4; p++) fma2(acc[r][p], w2, xp2[p]);
                }
            }
        }
        __syncthreads();
    }

    const int d  = d0 + dloc;
    const int pw = half*7 + pwl;
    #pragma unroll
    for (int r = 0; r < 8; r++) {
        float2 f0 = upk2(acc[r][0]);
        float mx = fmaxf(f0.x, f0.y);
        #pragma unroll
        for (int p = 1; p < 4; p++) {
            float2 fp = upk2(acc[r][p]);
            mx = fmaxf(mx, fmaxf(fp.x, fp.y));
        }
        mx = fmaxf(mx, __shfl_xor_sync(0xffffffffu, mx, 4));
        mx = fmaxf(mx, __shfl_xor_sync(0xffffffffu, mx, 2));
        mx = fmaxf(mx, __shfl_xor_sync(0xffffffffu, mx, 1));
        if (hh == 0) {
            int oc = ocg*8 + r;
            g_part[(((v*OCC + oc)*FPV + d)*14 + ph)*14 + pw] = mx;
        }
    }
}

// ================= D-pool + (pooled features) . lin_w -> g_fdot =================
__global__ void fdot_kernel(const float* __restrict__ cb, const float* __restrict__ lw)
{
    const int f = blockIdx.x;            // 256
    const int v = f >> 6, d = f & 63;
    const int tid = threadIdx.x;         // 256
    float acc[NCLS];
    #pragma unroll
    for (int c = 0; c < NCLS; c++) acc[c] = 0.f;

    for (int k = tid; k < 6272; k += 256) {
        int oc = k / 196; int rem2 = k % 196;
        const float* base = g_part + (v*OCC + oc)*FPV*196 + rem2;
        float val = base[d*196];
        if (d > 0)  val = fmaxf(val, base[(d-1)*196]);
        if (d < 63) val = fmaxf(val, base[(d+1)*196]);
        val += cb[oc];
        #pragma unroll
        for (int c = 0; c < NCLS; c++) acc[c] = fmaf(val, lw[c*6784 + k], acc[c]);
    }
    #pragma unroll
    for (int c = 0; c < NCLS; c++)
        for (int off = 16; off; off >>= 1)
            acc[c] += __shfl_xor_sync(0xffffffffu, acc[c], off);

    __shared__ float red[8][NCLS];
    const int wid = tid >> 5, lane = tid & 31;
    if (lane == 0)
        #pragma unroll
        for (int c = 0; c < NCLS; c++) red[wid][c] = acc[c];
    __syncthreads();
    if (tid < NCLS) {
        float s = 0.f;
        #pragma unroll
        for (int w = 0; w < 8; w++) s += red[w][tid];
        g_fdot[f*NCLS + tid] = s;
    }
}

// ================= Embedding gather (pad K to 304) =================
__global__ void embed_kernel(const int* __restrict__ txt, const float* __restrict__ emb)
{
    const int m = blockIdx.x;            // 7680 = row*32 + t
    const int tok = txt[m];
    const float* e = emb + (long long)tok * 300;
    for (int k = threadIdx.x; k < EPAD; k += 128)
        g_x0[m*EPAD + k] = (k < 300) ? e[k] : 0.f;
}

__global__ void pad_wih_kernel(const float* __restrict__ Wih0)
{
    const int row = blockIdx.x;          // 2048 = dir*1024 + gate
    const float* src = Wih0 + row * 300;
    for (int k = threadIdx.x; k < EPAD; k += 128)
        g_wpad[row*EPAD + k] = (k < 300) ? src[k] : 0.f;
}

// ================= SGEMM: pre = X @ Wih^T + bih + bhh =================
__global__ __launch_bounds__(256,2) void gemm_kernel(
    int layer, const float* __restrict__ Bext,
    const float* __restrict__ bih, const float* __restrict__ bhh)
{
    const int K = layer ? 512 : EPAD;
    const float* A = layer ? g_out0 : g_x0;
    const float* B = (layer ? Bext : (const float*)g_wpad) + blockIdx.z * 1024 * K;
    float* C = g_pre + blockIdx.z * (MROWS * 1024);
    const int m0 = blockIdx.x * 128, n0 = blockIdx.y * 128;

    __shared__ float As[8*132];
    __shared__ float Bs[8*132];
    const int tid = threadIdx.x;
    const int lr = tid >> 1;
    const int lk = (tid & 1) * 4;
    const int ty = tid >> 4, tx = tid & 15;
    const float* Arow = A + (m0 + lr)*K + lk;
    const float* Brow = B + (n0 + lr)*K + lk;

    u64 accp[8][4];
    #pragma unroll
    for (int i = 0; i < 8; i++)
        #pragma unroll
        for (int p = 0; p < 4; p++) accp[i][p] = 0ull;

    for (int k0 = 0; k0 < K; k0 += 8) {
        float4 va = *(const float4*)(Arow + k0);
        float4 vb = *(const float4*)(Brow + k0);
        __syncthreads();
        As[(lk+0)*132 + lr] = va.x; As[(lk+1)*132 + lr] = va.y;
        As[(lk+2)*132 + lr] = va.z; As[(lk+3)*132 + lr] = va.w;
        Bs[(lk+0)*132 + lr] = vb.x; Bs[(lk+1)*132 + lr] = vb.y;
        Bs[(lk+2)*132 + lr] = vb.z; Bs[(lk+3)*132 + lr] = vb.w;
        __syncthreads();
        #pragma unroll
        for (int kk = 0; kk < 8; kk++) {
            float a[8];
            float4 t0 = *(const float4*)&As[kk*132 + ty*8];
            float4 t1 = *(const float4*)&As[kk*132 + ty*8 + 4];
            float4 t2 = *(const float4*)&Bs[kk*132 + tx*8];
            float4 t3 = *(const float4*)&Bs[kk*132 + tx*8 + 4];
            a[0]=t0.x;a[1]=t0.y;a[2]=t0.z;a[3]=t0.w;a[4]=t1.x;a[5]=t1.y;a[6]=t1.z;a[7]=t1.w;
            u64 bp[4];
            bp[0] = pk2(t2.x, t2.y); bp[1] = pk2(t2.z, t2.w);
            bp[2] = pk2(t3.x, t3.y); bp[3] = pk2(t3.z, t3.w);
            #pragma unroll
            for (int i = 0; i < 8; i++) {
                u64 a2 = pk2(a[i], a[i]);
                #pragma unroll
                for (int p = 0; p < 4; p++) fma2(accp[i][p], a2, bp[p]);
            }
        }
    }
    float bb[8];
    #pragma unroll
    for (int j = 0; j < 8; j++) {
        int n = n0 + tx*8 + j;
        bb[j] = bih[blockIdx.z*1024 + n] + bhh[blockIdx.z*1024 + n];
    }
    #pragma unroll
    for (int i = 0; i < 8; i++) {
        float* crow = C + (m0 + ty*8 + i)*1024 + n0 + tx*8;
        #pragma unroll
        for (int p = 0; p < 4; p++) {
            float2 f = upk2(accp[i][p]);
            crow[2*p]   = f.x + bb[2*p];
            crow[2*p+1] = f.y + bb[2*p+1];
        }
    }
}

// ================= LSTM: persistent 32-step kernel =================
// grid (15 rowblocks, 4 j-slices, 2 dirs) = 120 CTAs (all resident), 256 threads.
// Cross-CTA sync per (dir,rowblock) group of 4 via g_sync counters (zeroed before launch).
__global__ void zero_sync_kernel()
{
    int i = threadIdx.x;
    if (i < 30) ((unsigned*)g_sync)[i] = 0u;
}

__global__ __launch_bounds__(256,1) void lstm_seq(
    int layer, const float* __restrict__ Whh, const int* __restrict__ lens)
{
    const int r0  = blockIdx.x * 16;
    const int j0  = blockIdx.y * 64;
    const int dir = blockIdx.z;
    const float* pre = g_pre + dir * (MROWS * 1024);
    float* outb = layer ? g_out1 : g_out0;

    __shared__ float hs2[256][18];   // [k][row-local], 8B-aligned row pairs
    __shared__ float zs[4][64][17];  // [gate][jl][row-local]
    __shared__ float cs[16][64];     // cell state, lives here all 32 steps
    const int tid = threadIdx.x;
    const int jl = tid & 63, gt = tid >> 6;
    const int gidx = gt*256 + j0 + jl;
    const float* wrow = Whh + dir*1024*256 + gidx*256;
    volatile unsigned* ctr = &g_sync[dir][blockIdx.x];

    for (int i = tid; i < 4096; i += 256) hs2[i & 255][i >> 8] = 0.f;
    for (int i = tid; i < 1024; i += 256) cs[i >> 6][i & 63] = 0.f;
    __syncthreads();

    for (int s = 0; s < 32; s++) {
        const int t = dir ? (31 - s) : s;

        u64 accp[8];
        #pragma unroll
        for (int q = 0; q < 8; q++)
            accp[q] = pk2(pre[((r0 + 2*q)*32 + t)*1024 + gidx],
                          pre[((r0 + 2*q + 1)*32 + t)*1024 + gidx]);

        #pragma unroll 2
        for (int k0 = 0; k0 < 256; k0 += 4) {
            float4 w = *(const float4*)(wrow + k0);
            float wk[4] = {w.x, w.y, w.z, w.w};
            #pragma unroll
            for (int kk = 0; kk < 4; kk++) {
                u64 w2 = pk2(wk[kk], wk[kk]);
                const u64* hrow = (const u64*)&hs2[k0 + kk][0];
                #pragma unroll
                for (int q = 0; q < 8; q++) fma2(accp[q], w2, hrow[q]);
            }
        }
        #pragma unroll
        for (int q = 0; q < 8; q++) {
            float2 f = upk2(accp[q]);
            zs[gt][jl][2*q]   = f.x;
            zs[gt][jl][2*q+1] = f.y;
        }
        __syncthreads();

        // pointwise: 64 jl x 16 rows = 1024 cells, 4 per thread
        float* hn = g_h[(s + 1) & 1][dir];
        #pragma unroll
        for (int q = 0; q < 4; q++) {
            int cell = tid + 256*q;
            int jl2 = cell & 63, rr = cell >> 6;
            int row = r0 + rr, j = j0 + jl2;
            float zi = zs[0][jl2][rr], zf = zs[1][jl2][rr];
            float zg = zs[2][jl2][rr], zo = zs[3][jl2][rr];
            float c_old = cs[rr][jl2];
            float h_old = hs2[j][rr];
            bool m = t < lens[row];
            float si = 1.f / (1.f + expf(-zi));
            float sf = 1.f / (1.f + expf(-zf));
            float so = 1.f / (1.f + expf(-zo));
            float cn = sf*c_old + si*tanhf(zg);
            float hv = so*tanhf(cn);
            cs[rr][jl2] = m ? cn : c_old;
            hn[row*256 + j] = m ? hv : h_old;
            outb[(row*32 + t)*512 + dir*256 + j] = m ? hv : 0.f;
        }

        if (s < 31) {
            __threadfence();                       // publish hn before arriving
            __syncthreads();                       // all threads' writes issued
            if (tid == 0) {
                atomicAdd((unsigned*)ctr, 1u);
                while (*ctr < 4u*(s + 1)) { }      // spin: 4 CTAs share this rowblock
            }
            __syncthreads();
            // reload h for next step (L2 reads: L1 is not coherent across SMs)
            const float* hp = g_h[(s + 1) & 1][dir];
            for (int i = tid; i < 4096; i += 256) {
                int r = i >> 8, k = i & 255;
                hs2[k][r] = __ldcg(&hp[(r0 + r)*256 + k]);
            }
            __syncthreads();
        }
    }
}

// ================= masked mean over time =================
__global__ void avg_kernel(const int* __restrict__ lens)
{
    const int row = blockIdx.x;   // 240
    const int k = threadIdx.x;    // 512
    float s = 0.f;
    for (int t = 0; t < 32; t++) s += g_out1[(row*32 + t)*512 + k];
    g_avg[row*512 + k] = s / (float)lens[row];
}

// ================= logits + per-video max + sigmoid =================
__global__ void final_kernel(const float* __restrict__ lw, const float* __restrict__ lb,
                             float* __restrict__ out)
{
    const int v = blockIdx.x / NCLS, c = blockIdx.x % NCLS;
    const int tid = threadIdx.x;  // 64
    float lg = -1e30f;
    if (tid < 60) {
        int rec = v*60 + tid;
        int sg = tid / 15, pp = tid % 15;
        int f = v*64 + sg*16 + pp;
        const float* av = g_avg + rec*512;
        const float* w  = lw + c*6784 + 6272;
        float dot = 0.f;
        #pragma unroll 4
        for (int k = 0; k < 512; k++) dot += av[k]*w[k];
        lg = 0.5f*(g_fdot[f*NCLS + c] + g_fdot[(f+1)*NCLS + c]) + dot + lb[c];
    }
    for (int off = 16; off; off >>= 1)
        lg = fmaxf(lg, __shfl_xor_sync(0xffffffffu, lg, off));
    __shared__ float red[2];
    if ((tid & 31) == 0) red[tid >> 5] = lg;
    __syncthreads();
    if (tid == 0) {
        float m = fmaxf(red[0], red[1]);
        out[v*NCLS + c] = 1.f / (1.f + expf(-m));
    }
}

// ================= launch =================
// Harness prepends 2 launches; ncu -s 5 -c 1 profiles overall #6 = MY #4 (conv).
extern "C" void kernel_launch(void* const* d_in, const int* in_sizes, int n_in,
                              void* d_out, int out_size)
{
    const float* img  = (const float*)d_in[0];
    const int*   txt  = (const int*)d_in[1];
    const int*   lens = (const int*)d_in[2];
    const float* emb  = (const float*)d_in[7];
    const float* Wih0 = (const float*)d_in[8];
    const float* Whh0 = (const float*)d_in[9];
    const float* bih0 = (const float*)d_in[10];
    const float* bhh0 = (const float*)d_in[11];
    const float* Wih1 = (const float*)d_in[12];
    const float* Whh1 = (const float*)d_in[13];
    const float* bih1 = (const float*)d_in[14];
    const float* bhh1 = (const float*)d_in[15];
    const float* cw   = (const float*)d_in[16];
    const float* cb   = (const float*)d_in[17];
    const float* lw   = (const float*)d_in[18];
    const float* lb   = (const float*)d_in[19];
    float* out = (float*)d_out;

    cudaFuncSetAttribute(conv_pool_kernel,
                         cudaFuncAttributeMaxDynamicSharedMemorySize, CONV_SMEM);

    pad_wih_kernel<<<2048, 128>>>(Wih0);                          // my #1
    embed_kernel<<<7680, 128>>>(txt, emb);                        // my #2
    gemm_kernel<<<dim3(60,8,2), 256>>>(0, (const float*)nullptr, bih0, bhh0); // my #3
    conv_pool_kernel<<<dim3(14,32,8), 448, CONV_SMEM>>>(img, cw); // my #4 <- profiled
    zero_sync_kernel<<<1, 32>>>();
    lstm_seq<<<dim3(15,4,2), 256>>>(0, Whh0, lens);
    fdot_kernel<<<256, 256>>>(cb, lw);
    gemm_kernel<<<dim3(60,8,2), 256>>>(1, Wih1, bih1, bhh1);
    zero_sync_kernel<<<1, 32>>>();
    lstm_seq<<<dim3(15,4,2), 256>>>(1, Whh1, lens);
    avg_kernel<<<240, 512>>>(lens);
    final_kernel<<<80, 64>>>(lw, lb, out);
}